// round 7
// baseline (speedup 1.0000x reference)
#include <cuda_runtime.h>
#include <math.h>

#define BATCH 64
#define SEQ   512
#define EMB   512
#define HID   1024
#define BH    (BATCH * HID)        // 65536
#define SBH   (SEQ * BH)           // 33554432
#define KSLICES 8
#define NBLOCKS 128                // persistent grid size (16 h-tiles x 8 k-slices)

// Scratch for per-step K-split partial sums: [KSLICES][BATCH][HID] = 2 MB
__device__ float g_partial[KSLICES * BH];
// Grid barrier state: [0] = arrive count, [1] = released phase
__device__ unsigned g_bar[2];

// ---------------------------------------------------------------------------
// Grid-wide barrier (all NBLOCKS CTAs co-resident). State reset per launch via
// cudaMemsetAsync, so phase counts monotonically 1..N within one launch.
// ---------------------------------------------------------------------------
__device__ __forceinline__ void gridbar(unsigned& myphase) {
    __threadfence();           // make this thread's prior global writes visible device-wide
    __syncthreads();           // all threads of the block fenced + arrived
    if (threadIdx.x == 0) {
        unsigned target = myphase + 1u;
        if (atomicAdd(&g_bar[0], 1u) == (NBLOCKS - 1u)) {
            g_bar[0] = 0u;     // reset count for next barrier
            __threadfence();   // count reset visible before release observed
            atomicExch(&g_bar[1], target);
        } else {
            while (atomicAdd(&g_bar[1], 0u) < target) { __nanosleep(64); }
        }
    }
    __syncthreads();
    myphase++;
}

// ---------------------------------------------------------------------------
// Kernel 1: xproj[s][b][h] = sum_e X[b][s][e] * Wax[h][e] + ba[h]
// Written directly into the outputs region of d_out.
// 128x128 block tile, BK=8, 256 threads, 8x8 per thread (4+4 split at +64).
// ---------------------------------------------------------------------------
__global__ __launch_bounds__(256) void xproj_kernel(
    const float* __restrict__ X, const float* __restrict__ Wax,
    const float* __restrict__ ba, float* __restrict__ out)
{
    __shared__ float As[8][128];
    __shared__ float Bs[8][128];

    const int tid = threadIdx.x;
    const int r0 = blockIdx.x * 128;   // row = s*BATCH + b
    const int h0 = blockIdx.y * 128;

    // Loader mapping: each thread loads one float4 of A and one of B per k-tile
    const int lr = tid >> 1;           // 0..127
    const int lk = (tid & 1) * 4;      // 0 or 4
    const int r  = r0 + lr;
    const float* Aptr = X + (size_t)(r & (BATCH - 1)) * (SEQ * EMB)
                          + (size_t)(r >> 6) * EMB + lk;
    const float* Bptr = Wax + (size_t)(h0 + lr) * EMB + lk;

    const int tm0 = (tid >> 4) * 4;    // 0..60 (row group, second group at +64)
    const int tn0 = (tid & 15) * 4;    // 0..60 (col group, second group at +64)

    float acc[8][8];
#pragma unroll
    for (int i = 0; i < 8; i++)
#pragma unroll
        for (int j = 0; j < 8; j++) acc[i][j] = 0.0f;

    for (int k0 = 0; k0 < EMB; k0 += 8) {
        float4 av = *(const float4*)(Aptr + k0);
        float4 bv = *(const float4*)(Bptr + k0);
        As[lk + 0][lr] = av.x; As[lk + 1][lr] = av.y;
        As[lk + 2][lr] = av.z; As[lk + 3][lr] = av.w;
        Bs[lk + 0][lr] = bv.x; Bs[lk + 1][lr] = bv.y;
        Bs[lk + 2][lr] = bv.z; Bs[lk + 3][lr] = bv.w;
        __syncthreads();

#pragma unroll
        for (int k = 0; k < 8; k++) {
            float4 a0 = *(const float4*)&As[k][tm0];
            float4 a1 = *(const float4*)&As[k][tm0 + 64];
            float4 b0 = *(const float4*)&Bs[k][tn0];
            float4 b1 = *(const float4*)&Bs[k][tn0 + 64];
            float ar[8] = {a0.x, a0.y, a0.z, a0.w, a1.x, a1.y, a1.z, a1.w};
            float br[8] = {b0.x, b0.y, b0.z, b0.w, b1.x, b1.y, b1.z, b1.w};
#pragma unroll
            for (int i = 0; i < 8; i++)
#pragma unroll
                for (int j = 0; j < 8; j++) acc[i][j] += ar[i] * br[j];
        }
        __syncthreads();
    }

    // Epilogue: add bias, store
    float bav[8];
#pragma unroll
    for (int j = 0; j < 4; j++) {
        bav[j]     = ba[h0 + tn0 + j];
        bav[4 + j] = ba[h0 + tn0 + 64 + j];
    }
#pragma unroll
    for (int gi = 0; gi < 2; gi++) {
#pragma unroll
        for (int ii = 0; ii < 4; ii++) {
            int i = gi * 4 + ii;
            int row = r0 + tm0 + gi * 64 + ii;
            float* o = out + (size_t)row * HID + h0;
            float4 v0 = make_float4(acc[i][0] + bav[0], acc[i][1] + bav[1],
                                    acc[i][2] + bav[2], acc[i][3] + bav[3]);
            float4 v1 = make_float4(acc[i][4] + bav[4], acc[i][5] + bav[5],
                                    acc[i][6] + bav[6], acc[i][7] + bav[7]);
            *(float4*)(o + tn0)      = v0;
            *(float4*)(o + tn0 + 64) = v1;
        }
    }
}

// ---------------------------------------------------------------------------
// Kernel 2: persistent recurrence. 128 CTAs x 256 threads.
// CTA bi owns h-tile ht=bi%16 (64 cols) and k-slice ks=bi/16 (128 ks).
// W_aa slice (64x128 fp32 = 32KB) lives in smem for all 512 steps.
// Per step s>=1:
//   phase1: partial[ks][b][h] = sum_{k in slice} a_{s-1}[b][k] * Waa[h][k]
//   gridbar
//   phase2: out[s] = tanh(out[s] (=xproj) + sum_ks partial)   (block-sliced)
//   gridbar
// Step 0: out[0] = tanh(xproj[0])  (a_0 = 0).
// ---------------------------------------------------------------------------
__global__ __launch_bounds__(256) void rnn_persistent(
    const float* __restrict__ Waa, float* __restrict__ outs, int write_hidden)
{
    __shared__ float Ws[128][64];   // [k_local][h_local], 32 KB
    __shared__ float As[16][64];    // staged a tile [k_local16][b], 4 KB

    const int tid = threadIdx.x;
    const int bi  = blockIdx.x;           // 0..127
    const int ht  = bi & 15;
    const int ks  = bi >> 4;
    const int h0  = ht * 64;
    const int k0  = ks * 128;

    // Load W slice once: Waa[h0+h][k0+k] -> Ws[k][h]
    for (int i = tid; i < 64 * 32; i += 256) {
        int h  = i >> 5;                   // 0..63
        int kq = (i & 31) * 4;             // 0..124
        float4 w = *(const float4*)(Waa + (size_t)(h0 + h) * HID + k0 + kq);
        Ws[kq + 0][h] = w.x; Ws[kq + 1][h] = w.y;
        Ws[kq + 2][h] = w.z; Ws[kq + 3][h] = w.w;
    }
    __syncthreads();

    const int tm0 = (tid >> 4) * 4;        // b group
    const int tn0 = (tid & 15) * 4;        // h group
    const int lb  = tid >> 2;              // loader b 0..63
    const int lk  = (tid & 3) * 4;         // loader k 0,4,8,12

    unsigned myphase = 0;

    for (int s = 0; s < SEQ; s++) {
        if (s > 0) {
            const float* aprev = outs + (size_t)(s - 1) * BH;
            float acc[4][4];
#pragma unroll
            for (int i = 0; i < 4; i++)
#pragma unroll
                for (int j = 0; j < 4; j++) acc[i][j] = 0.0f;

#pragma unroll 1
            for (int kt = 0; kt < 8; kt++) {
                float4 av = *(const float4*)(aprev + (size_t)lb * HID
                                             + k0 + kt * 16 + lk);
                __syncthreads();           // prior reads of As done
                As[lk + 0][lb] = av.x; As[lk + 1][lb] = av.y;
                As[lk + 2][lb] = av.z; As[lk + 3][lb] = av.w;
                __syncthreads();
#pragma unroll
                for (int k = 0; k < 16; k++) {
                    float4 a4 = *(const float4*)&As[k][tm0];
                    float4 w4 = *(const float4*)&Ws[kt * 16 + k][tn0];
                    float ar[4] = {a4.x, a4.y, a4.z, a4.w};
                    float wr[4] = {w4.x, w4.y, w4.z, w4.w};
#pragma unroll
                    for (int i = 0; i < 4; i++)
#pragma unroll
                        for (int j = 0; j < 4; j++) acc[i][j] += ar[i] * wr[j];
                }
            }
            // write partial slice
#pragma unroll
            for (int i = 0; i < 4; i++) {
                *(float4*)(g_partial + (size_t)ks * BH
                           + (size_t)(tm0 + i) * HID + h0 + tn0)
                    = make_float4(acc[i][0], acc[i][1], acc[i][2], acc[i][3]);
            }
            gridbar(myphase);
        }

        // phase2: combine + tanh on this block's 512-element slice of out[s]
        {
            const size_t sbase = (size_t)s * BH;
#pragma unroll
            for (int t = 0; t < 2; t++) {
                int idx = bi * 512 + t * 256 + tid;
                float v = outs[sbase + idx];
                if (s > 0) {
#pragma unroll
                    for (int p = 0; p < KSLICES; p++)
                        v += __ldcg(g_partial + (size_t)p * BH + idx);
                }
                outs[sbase + idx] = tanhf(v);
            }
        }
        gridbar(myphase);
    }

    // Final hidden = outputs[SEQ-1] appended after the outputs region
    if (write_hidden) {
#pragma unroll
        for (int t = 0; t < 2; t++) {
            int idx = bi * 512 + t * 256 + tid;
            outs[(size_t)SBH + idx] = outs[(size_t)(SEQ - 1) * BH + idx];
        }
    }
}

// ---------------------------------------------------------------------------
// Launch. Inputs (metadata order): X [B,S,E] f32, W_ax [H,E] f32,
// W_aa [H,H] f32, b_a [H] f32. Output: outputs [S,B,H] then hidden [B,H].
// ---------------------------------------------------------------------------
extern "C" void kernel_launch(void* const* d_in, const int* in_sizes, int n_in,
                              void* d_out, int out_size) {
    (void)in_sizes; (void)n_in;
    const float* X   = (const float*)d_in[0];
    const float* Wax = (const float*)d_in[1];
    const float* Waa = (const float*)d_in[2];
    const float* ba  = (const float*)d_in[3];
    float* out = (float*)d_out;

    // Reset grid-barrier state (graph-capturable memset node, runs every replay)
    void* barp = nullptr;
    cudaGetSymbolAddress(&barp, g_bar);
    cudaMemsetAsync(barp, 0, 2 * sizeof(unsigned), 0);

    // 1) xproj into the outputs region of d_out
    dim3 g1((SEQ * BATCH) / 128, HID / 128);
    xproj_kernel<<<g1, 256>>>(X, Wax, ba, out);

    // 2) persistent recurrence (in-place over d_out timesteps)
    int write_hidden = (out_size >= (int)(SBH + BH)) ? 1 : 0;
    rnn_persistent<<<NBLOCKS, 256>>>(Waa, out, write_hidden);
}

// round 8
// speedup vs baseline: 1.0521x; 1.0521x over previous
#include <cuda_runtime.h>
#include <math.h>

#define BATCH 64
#define SEQ   512
#define EMB   512
#define HID   1024
#define BH    (BATCH * HID)        // 65536
#define SBH   (SEQ * BH)           // 33554432
#define KSLICES 8
#define NBLOCKS 128                // persistent grid (16 h-tiles x 8 k-slices)

typedef unsigned long long u64;

// Scratch for per-step K-split partial sums: [KSLICES][BATCH][HID] = 2 MB
__device__ float g_partial[KSLICES * BH];
// Grid barrier state: [0] = arrive count, [1] = released phase
__device__ unsigned g_bar[2];

// ---------------- packed fp32x2 helpers (sm_100+/sm_103a) -------------------
__device__ __forceinline__ u64 pkdup(float x) {
    u64 r; asm("mov.b64 %0, {%1, %1};" : "=l"(r) : "f"(x)); return r;
}
__device__ __forceinline__ void fma2(u64& d, u64 a, u64 b) {
    asm("fma.rn.f32x2 %0, %1, %2, %0;" : "+l"(d) : "l"(a), "l"(b));
}
__device__ __forceinline__ float2 un2(u64 v) {
    float2 f; asm("mov.b64 {%0, %1}, %2;" : "=f"(f.x), "=f"(f.y) : "l"(v));
    return f;
}

// ---------------------------------------------------------------------------
// Grid-wide barrier: arrive via one atomic per CTA; release observed with a
// plain volatile load (no atomic-poll serialization at the LTS). Release chain
// is valid per the PTX model: writers' STG -> __syncthreads (cta-visible) ->
// t0 fence.sc.gpu (cumulative) -> release store; waiter: volatile load ->
// fence -> __syncthreads.
// ---------------------------------------------------------------------------
__device__ __forceinline__ void gridbar(unsigned& myphase) {
    __syncthreads();
    if (threadIdx.x == 0) {
        __threadfence();
        unsigned target = myphase + 1u;
        if (atomicAdd(&g_bar[0], 1u) == (NBLOCKS - 1u)) {
            g_bar[0] = 0u;
            __threadfence();
            atomicExch(&g_bar[1], target);
        } else {
            while (*((volatile unsigned*)&g_bar[1]) < target) { }
        }
        __threadfence();
    }
    __syncthreads();
    myphase++;
}

// ---------------------------------------------------------------------------
// Kernel 1: xproj[s][b][h] = sum_e X[b][s][e] * Wax[h][e] + ba[h]
// 128x128 tile, BK=8, 256 threads, 8x8 per thread, f32x2 packed inner loop.
// ---------------------------------------------------------------------------
__global__ __launch_bounds__(256) void xproj_kernel(
    const float* __restrict__ X, const float* __restrict__ Wax,
    const float* __restrict__ ba, float* __restrict__ out)
{
    __shared__ float As[8][128];
    __shared__ float Bs[8][128];

    const int tid = threadIdx.x;
    const int r0 = blockIdx.x * 128;   // row = s*BATCH + b
    const int h0 = blockIdx.y * 128;

    const int lr = tid >> 1;           // 0..127
    const int lk = (tid & 1) * 4;      // 0 or 4
    const int r  = r0 + lr;
    const float* Aptr = X + (size_t)(r & (BATCH - 1)) * (SEQ * EMB)
                          + (size_t)(r >> 6) * EMB + lk;
    const float* Bptr = Wax + (size_t)(h0 + lr) * EMB + lk;

    const int tm0 = (tid >> 4) * 4;
    const int tn0 = (tid & 15) * 4;

    // acc[i][p]: row i (0..3 -> tm0+i, 4..7 -> tm0+64+i), p = h-pair
    // p=0: tn0+{0,1}; p=1: tn0+{2,3}; p=2: tn0+64+{0,1}; p=3: tn0+64+{2,3}
    u64 acc[8][4];
#pragma unroll
    for (int i = 0; i < 8; i++)
#pragma unroll
        for (int p = 0; p < 4; p++) acc[i][p] = 0ull;

    for (int k0 = 0; k0 < EMB; k0 += 8) {
        float4 av = *(const float4*)(Aptr + k0);
        float4 bv = *(const float4*)(Bptr + k0);
        As[lk + 0][lr] = av.x; As[lk + 1][lr] = av.y;
        As[lk + 2][lr] = av.z; As[lk + 3][lr] = av.w;
        Bs[lk + 0][lr] = bv.x; Bs[lk + 1][lr] = bv.y;
        Bs[lk + 2][lr] = bv.z; Bs[lk + 3][lr] = bv.w;
        __syncthreads();

#pragma unroll
        for (int k = 0; k < 8; k++) {
            float4 a0 = *(const float4*)&As[k][tm0];
            float4 a1 = *(const float4*)&As[k][tm0 + 64];
            ulonglong2 wA = *(const ulonglong2*)&Bs[k][tn0];
            ulonglong2 wB = *(const ulonglong2*)&Bs[k][tn0 + 64];
            float ar[8] = {a0.x, a0.y, a0.z, a0.w, a1.x, a1.y, a1.z, a1.w};
#pragma unroll
            for (int i = 0; i < 8; i++) {
                u64 ai = pkdup(ar[i]);
                fma2(acc[i][0], ai, wA.x);
                fma2(acc[i][1], ai, wA.y);
                fma2(acc[i][2], ai, wB.x);
                fma2(acc[i][3], ai, wB.y);
            }
        }
        __syncthreads();
    }

    float bav[8];
#pragma unroll
    for (int j = 0; j < 4; j++) {
        bav[j]     = ba[h0 + tn0 + j];
        bav[4 + j] = ba[h0 + tn0 + 64 + j];
    }
#pragma unroll
    for (int gi = 0; gi < 2; gi++) {
#pragma unroll
        for (int ii = 0; ii < 4; ii++) {
            int i = gi * 4 + ii;
            int row = r0 + tm0 + gi * 64 + ii;
            float* o = out + (size_t)row * HID + h0;
            float2 p0 = un2(acc[i][0]), p1 = un2(acc[i][1]);
            float2 p2 = un2(acc[i][2]), p3 = un2(acc[i][3]);
            float4 v0 = make_float4(p0.x + bav[0], p0.y + bav[1],
                                    p1.x + bav[2], p1.y + bav[3]);
            float4 v1 = make_float4(p2.x + bav[4], p2.y + bav[5],
                                    p3.x + bav[6], p3.y + bav[7]);
            *(float4*)(o + tn0)      = v0;
            *(float4*)(o + tn0 + 64) = v1;
        }
    }
}

// ---------------------------------------------------------------------------
// Kernel 2: persistent recurrence. 128 CTAs x 256 threads.
// CTA bi owns h-tile ht=bi%16 (64 cols) and k-slice ks=bi/16 (128 ks).
// W_aa slice (64x128 fp32 = 32KB) resident in smem for all 512 steps.
// Per step s>=1:
//   phase1: partial[ks][b][h] = sum_{k in slice} a_{s-1}[b][k] * Waa[h][k]
//           (double-buffered 16-k chunks, f32x2 packed math)
//   gridbar; phase2: out[s] = tanh(xproj + sum_ks partial); gridbar
// ---------------------------------------------------------------------------
__global__ __launch_bounds__(256) void rnn_persistent(
    const float* __restrict__ Waa, float* __restrict__ outs, int write_hidden)
{
    __shared__ float Ws[128][64];      // [k_local][h_local], 32 KB
    __shared__ float As[2][16][64];    // double-buffered a chunk, 8 KB

    const int tid = threadIdx.x;
    const int bi  = blockIdx.x;
    const int ht  = bi & 15;
    const int ks  = bi >> 4;
    const int h0  = ht * 64;
    const int k0  = ks * 128;

    // Load W slice once: Waa[h0+h][k0+k] -> Ws[k][h]
    for (int i = tid; i < 64 * 32; i += 256) {
        int h  = i >> 5;
        int kq = (i & 31) * 4;
        float4 w = *(const float4*)(Waa + (size_t)(h0 + h) * HID + k0 + kq);
        Ws[kq + 0][h] = w.x; Ws[kq + 1][h] = w.y;
        Ws[kq + 2][h] = w.z; Ws[kq + 3][h] = w.w;
    }
    __syncthreads();

    const int tm0 = (tid >> 4) * 4;    // b group
    const int tn0 = (tid & 15) * 4;    // h group
    const int lb  = tid >> 2;          // loader b 0..63
    const int lk  = (tid & 3) * 4;     // loader k 0,4,8,12

    unsigned myphase = 0;

    for (int s = 0; s < SEQ; s++) {
        if (s > 0) {
            const float* aprev = outs + (size_t)(s - 1) * BH;
            const float* aRow  = aprev + (size_t)lb * HID + k0 + lk;

            // acc[i][p]: b = tm0+i; p=0 -> h0+tn0+{0,1}, p=1 -> h0+tn0+{2,3}
            u64 acc[4][2];
#pragma unroll
            for (int i = 0; i < 4; i++) { acc[i][0] = 0ull; acc[i][1] = 0ull; }

            // preload chunk 0
            {
                float4 av = *(const float4*)(aRow);
                As[0][lk + 0][lb] = av.x; As[0][lk + 1][lb] = av.y;
                As[0][lk + 2][lb] = av.z; As[0][lk + 3][lb] = av.w;
            }
            __syncthreads();

#pragma unroll 1
            for (int kt = 0; kt < 8; kt++) {
                if (kt < 7) {
                    // buffer (kt+1)&1 was last READ in iter kt-1, before the
                    // trailing __syncthreads -> safe to overwrite now.
                    float4 nv = *(const float4*)(aRow + (kt + 1) * 16);
                    const int nb = (kt + 1) & 1;
                    As[nb][lk + 0][lb] = nv.x; As[nb][lk + 1][lb] = nv.y;
                    As[nb][lk + 2][lb] = nv.z; As[nb][lk + 3][lb] = nv.w;
                }
                const int cur = kt & 1;
                const float (*Wrow)[64] = &Ws[kt * 16];
#pragma unroll
                for (int k = 0; k < 16; k++) {
                    float4 a4 = *(const float4*)&As[cur][k][tm0];
                    ulonglong2 w2 = *(const ulonglong2*)&Wrow[k][tn0];
                    u64 ai;
                    ai = pkdup(a4.x); fma2(acc[0][0], ai, w2.x); fma2(acc[0][1], ai, w2.y);
                    ai = pkdup(a4.y); fma2(acc[1][0], ai, w2.x); fma2(acc[1][1], ai, w2.y);
                    ai = pkdup(a4.z); fma2(acc[2][0], ai, w2.x); fma2(acc[2][1], ai, w2.y);
                    ai = pkdup(a4.w); fma2(acc[3][0], ai, w2.x); fma2(acc[3][1], ai, w2.y);
                }
                __syncthreads();
            }

            // write partial slice
#pragma unroll
            for (int i = 0; i < 4; i++) {
                float2 pa = un2(acc[i][0]);
                float2 pb = un2(acc[i][1]);
                *(float4*)(g_partial + (size_t)ks * BH
                           + (size_t)(tm0 + i) * HID + h0 + tn0)
                    = make_float4(pa.x, pa.y, pb.x, pb.y);
            }
            gridbar(myphase);
        }

        // phase2: combine + tanh on this block's 512-element slice of out[s]
        {
            const size_t sbase = (size_t)s * BH;
#pragma unroll
            for (int t = 0; t < 2; t++) {
                int idx = bi * 512 + t * 256 + tid;
                float v = outs[sbase + idx];
                if (s > 0) {
#pragma unroll
                    for (int p = 0; p < KSLICES; p++)
                        v += __ldcg(g_partial + (size_t)p * BH + idx);
                }
                outs[sbase + idx] = tanhf(v);
            }
        }
        gridbar(myphase);
    }

    // Final hidden = outputs[SEQ-1] appended after the outputs region
    if (write_hidden) {
#pragma unroll
        for (int t = 0; t < 2; t++) {
            int idx = bi * 512 + t * 256 + tid;
            outs[(size_t)SBH + idx] = outs[(size_t)(SEQ - 1) * BH + idx];
        }
    }
}

// ---------------------------------------------------------------------------
// Launch. Inputs: X [B,S,E] f32, W_ax [H,E] f32, W_aa [H,H] f32, b_a [H] f32.
// Output: outputs [S,B,H] then hidden [B,H].
// ---------------------------------------------------------------------------
extern "C" void kernel_launch(void* const* d_in, const int* in_sizes, int n_in,
                              void* d_out, int out_size) {
    (void)in_sizes; (void)n_in;
    const float* X   = (const float*)d_in[0];
    const float* Wax = (const float*)d_in[1];
    const float* Waa = (const float*)d_in[2];
    const float* ba  = (const float*)d_in[3];
    float* out = (float*)d_out;

    void* barp = nullptr;
    cudaGetSymbolAddress(&barp, g_bar);
    cudaMemsetAsync(barp, 0, 2 * sizeof(unsigned), 0);

    dim3 g1((SEQ * BATCH) / 128, HID / 128);
    xproj_kernel<<<g1, 256>>>(X, Wax, ba, out);

    int write_hidden = (out_size >= (int)(SBH + BH)) ? 1 : 0;
    rnn_persistent<<<NBLOCKS, 256>>>(Waa, out, write_hidden);
}

// round 9
// speedup vs baseline: 1.2873x; 1.2235x over previous
#include <cuda_runtime.h>
#include <math.h>

#define BATCH 64
#define SEQ   512
#define EMB   512
#define HID   1024
#define BH    (BATCH * HID)        // 65536
#define SBH   (SEQ * BH)           // 33554432
#define KSLICES 32
#define NBLOCKS 128                // persistent grid (4 h-tiles x 32 k-slices)

typedef unsigned long long u64;

// Per-step K-split partials: [KSLICES][BATCH][HID] = 8 MB
__device__ float g_partial[KSLICES * BH];
// Distributed barrier counters: 4 counters, 256B apart (distinct LTS slices)
__device__ unsigned g_cnt[256];

// ---------------- packed fp32x2 helpers (sm_103a) ---------------------------
__device__ __forceinline__ u64 pkdup(float x) {
    u64 r; asm("mov.b64 %0, {%1, %1};" : "=l"(r) : "f"(x)); return r;
}
__device__ __forceinline__ void fma2(u64& d, u64 a, u64 b) {
    asm("fma.rn.f32x2 %0, %1, %2, %0;" : "+l"(d) : "l"(a), "l"(b));
}

// ---------------------------------------------------------------------------
// Distributed grid barrier. CTA bi arrives on counter (bi&3) with a
// release-add; waiters acquire-load all 4 counters until each reaches
// 32*phase. Release-add + acquire-load gives the cross-CTA happens-before
// (cumulative over the preceding __syncthreads). Counters zeroed per launch.
// ---------------------------------------------------------------------------
__device__ __forceinline__ void gridbar(unsigned& phase) {
    phase++;
    const unsigned target = phase * 32u;
    __syncthreads();
    if (threadIdx.x == 0) {
        unsigned* my = &g_cnt[(blockIdx.x & 3) * 64];
        asm volatile("red.release.gpu.global.add.u32 [%0], %1;"
                     :: "l"(my), "r"(1u) : "memory");
        unsigned c0, c1, c2, c3;
        do {
            asm volatile("ld.acquire.gpu.global.u32 %0, [%1];" : "=r"(c0) : "l"(&g_cnt[0]));
            asm volatile("ld.acquire.gpu.global.u32 %0, [%1];" : "=r"(c1) : "l"(&g_cnt[64]));
            asm volatile("ld.acquire.gpu.global.u32 %0, [%1];" : "=r"(c2) : "l"(&g_cnt[128]));
            asm volatile("ld.acquire.gpu.global.u32 %0, [%1];" : "=r"(c3) : "l"(&g_cnt[192]));
        } while (c0 < target || c1 < target || c2 < target || c3 < target);
    }
    __syncthreads();
}

// ---------------------------------------------------------------------------
// Kernel 1: xproj[s][b][h] = sum_e X[b][s][e] * Wax[h][e] + ba[h]   (as R8)
// ---------------------------------------------------------------------------
__global__ __launch_bounds__(256) void xproj_kernel(
    const float* __restrict__ X, const float* __restrict__ Wax,
    const float* __restrict__ ba, float* __restrict__ out)
{
    __shared__ float As[8][128];
    __shared__ float Bs[8][128];

    const int tid = threadIdx.x;
    const int r0 = blockIdx.x * 128;
    const int h0 = blockIdx.y * 128;

    const int lr = tid >> 1;
    const int lk = (tid & 1) * 4;
    const int r  = r0 + lr;
    const float* Aptr = X + (size_t)(r & (BATCH - 1)) * (SEQ * EMB)
                          + (size_t)(r >> 6) * EMB + lk;
    const float* Bptr = Wax + (size_t)(h0 + lr) * EMB + lk;

    const int tm0 = (tid >> 4) * 4;
    const int tn0 = (tid & 15) * 4;

    u64 acc[8][4];
#pragma unroll
    for (int i = 0; i < 8; i++)
#pragma unroll
        for (int p = 0; p < 4; p++) acc[i][p] = 0ull;

    for (int k0 = 0; k0 < EMB; k0 += 8) {
        float4 av = *(const float4*)(Aptr + k0);
        float4 bv = *(const float4*)(Bptr + k0);
        As[lk + 0][lr] = av.x; As[lk + 1][lr] = av.y;
        As[lk + 2][lr] = av.z; As[lk + 3][lr] = av.w;
        Bs[lk + 0][lr] = bv.x; Bs[lk + 1][lr] = bv.y;
        Bs[lk + 2][lr] = bv.z; Bs[lk + 3][lr] = bv.w;
        __syncthreads();

#pragma unroll
        for (int k = 0; k < 8; k++) {
            float4 a0 = *(const float4*)&As[k][tm0];
            float4 a1 = *(const float4*)&As[k][tm0 + 64];
            ulonglong2 wA = *(const ulonglong2*)&Bs[k][tn0];
            ulonglong2 wB = *(const ulonglong2*)&Bs[k][tn0 + 64];
            float ar[8] = {a0.x, a0.y, a0.z, a0.w, a1.x, a1.y, a1.z, a1.w};
#pragma unroll
            for (int i = 0; i < 8; i++) {
                u64 ai = pkdup(ar[i]);
                fma2(acc[i][0], ai, wA.x);
                fma2(acc[i][1], ai, wA.y);
                fma2(acc[i][2], ai, wB.x);
                fma2(acc[i][3], ai, wB.y);
            }
        }
        __syncthreads();
    }

    float bav[8];
#pragma unroll
    for (int j = 0; j < 4; j++) {
        bav[j]     = ba[h0 + tn0 + j];
        bav[4 + j] = ba[h0 + tn0 + 64 + j];
    }
#pragma unroll
    for (int gi = 0; gi < 2; gi++) {
#pragma unroll
        for (int ii = 0; ii < 4; ii++) {
            int i = gi * 4 + ii;
            int row = r0 + tm0 + gi * 64 + ii;
            float* o = out + (size_t)row * HID + h0;
            float2 p0 = *(float2*)&acc[i][0], p1 = *(float2*)&acc[i][1];
            float2 p2 = *(float2*)&acc[i][2], p3 = *(float2*)&acc[i][3];
            *(float4*)(o + tn0)      = make_float4(p0.x + bav[0], p0.y + bav[1],
                                                   p1.x + bav[2], p1.y + bav[3]);
            *(float4*)(o + tn0 + 64) = make_float4(p2.x + bav[4], p2.y + bav[5],
                                                   p3.x + bav[6], p3.y + bav[7]);
        }
    }
}

// ---------------------------------------------------------------------------
// Kernel 2: persistent recurrence. 128 CTAs x 256 threads.
// CTA bi: h-tile ht=bi>>5 (256 h), k-slice ks=bi&31 (32 k).
// W slice Ws[32k][256h] (32 KB) resident in smem all 512 steps.
// Thread tile: 8b (warp-shared, broadcast LDS) x 8h (2 float4 chunks at
// lane*4 and 128+lane*4). Whole a-slice staged once per step (2 syncs).
// ---------------------------------------------------------------------------
__global__ __launch_bounds__(256) void rnn_persistent(
    const float* __restrict__ Waa, float* __restrict__ outs, int write_hidden)
{
    __shared__ float Ws[32][256];      // [k][h], 32 KB
    __shared__ float As[32][68];       // [k][b], padded (bank + 16B align)

    const int tid   = threadIdx.x;
    const int bi    = blockIdx.x;
    const int ht    = bi >> 5;         // 0..3
    const int ks    = bi & 31;         // 0..31
    const int h0    = ht * 256;
    const int k0    = ks * 32;
    const int lane4 = (tid & 31) * 4;  // h chunk base within 128
    const int b0    = (tid >> 5) * 8;  // warp's 8 batch rows

    // Load W slice once: Ws[k][h] = Waa[h0+h][k0+k]
    {
        const float* wrow = Waa + (size_t)(h0 + tid) * HID + k0;
#pragma unroll
        for (int j = 0; j < 8; j++) {
            float4 w = *(const float4*)(wrow + j * 4);
            Ws[j * 4 + 0][tid] = w.x; Ws[j * 4 + 1][tid] = w.y;
            Ws[j * 4 + 2][tid] = w.z; Ws[j * 4 + 3][tid] = w.w;
        }
    }
    __syncthreads();

    // Staging map: thread t -> b = t>>2 (0..63), k-chunk = (t&3)*8
    const int sb = tid >> 2;
    const int sk = (tid & 3) * 8;

    unsigned phase = 0;

    for (int s = 0; s < SEQ; s++) {
        if (s > 0) {
            // ---- stage a_{s-1} slice [64b x 32k], transposed into As[k][b]
            const float* ap = outs + (size_t)(s - 1) * BH + (size_t)sb * HID + k0 + sk;
            float4 a0 = *(const float4*)ap;
            float4 a1 = *(const float4*)(ap + 4);
            // previous readers of As finished before last gridbar's syncthreads
            As[sk + 0][sb] = a0.x; As[sk + 1][sb] = a0.y;
            As[sk + 2][sb] = a0.z; As[sk + 3][sb] = a0.w;
            As[sk + 4][sb] = a1.x; As[sk + 5][sb] = a1.y;
            As[sk + 6][sb] = a1.z; As[sk + 7][sb] = a1.w;
            __syncthreads();

            // ---- compute: acc[8b][8h]  (h pairs packed in u64)
            u64 acc[8][4];
#pragma unroll
            for (int i = 0; i < 8; i++)
#pragma unroll
                for (int p = 0; p < 4; p++) acc[i][p] = 0ull;

#pragma unroll 8
            for (int k = 0; k < 32; k++) {
                ulonglong2 wA = *(const ulonglong2*)&Ws[k][lane4];
                ulonglong2 wB = *(const ulonglong2*)&Ws[k][128 + lane4];
                const float* ar = &As[k][b0];      // warp-uniform (broadcast)
                float4 aa = *(const float4*)ar;
                float4 ab = *(const float4*)(ar + 4);
                u64 d;
                d = pkdup(aa.x); fma2(acc[0][0], d, wA.x); fma2(acc[0][1], d, wA.y);
                                 fma2(acc[0][2], d, wB.x); fma2(acc[0][3], d, wB.y);
                d = pkdup(aa.y); fma2(acc[1][0], d, wA.x); fma2(acc[1][1], d, wA.y);
                                 fma2(acc[1][2], d, wB.x); fma2(acc[1][3], d, wB.y);
                d = pkdup(aa.z); fma2(acc[2][0], d, wA.x); fma2(acc[2][1], d, wA.y);
                                 fma2(acc[2][2], d, wB.x); fma2(acc[2][3], d, wB.y);
                d = pkdup(aa.w); fma2(acc[3][0], d, wA.x); fma2(acc[3][1], d, wA.y);
                                 fma2(acc[3][2], d, wB.x); fma2(acc[3][3], d, wB.y);
                d = pkdup(ab.x); fma2(acc[4][0], d, wA.x); fma2(acc[4][1], d, wA.y);
                                 fma2(acc[4][2], d, wB.x); fma2(acc[4][3], d, wB.y);
                d = pkdup(ab.y); fma2(acc[5][0], d, wA.x); fma2(acc[5][1], d, wA.y);
                                 fma2(acc[5][2], d, wB.x); fma2(acc[5][3], d, wB.y);
                d = pkdup(ab.z); fma2(acc[6][0], d, wA.x); fma2(acc[6][1], d, wA.y);
                                 fma2(acc[6][2], d, wB.x); fma2(acc[6][3], d, wB.y);
                d = pkdup(ab.w); fma2(acc[7][0], d, wA.x); fma2(acc[7][1], d, wA.y);
                                 fma2(acc[7][2], d, wB.x); fma2(acc[7][3], d, wB.y);
            }

            // ---- write partials: [ks][b][h], coalesced per (b, chunk)
            float* gp0 = g_partial + (size_t)ks * BH + (size_t)b0 * HID + h0 + lane4;
#pragma unroll
            for (int i = 0; i < 8; i++) {
                float* gp = gp0 + (size_t)i * HID;
                *(ulonglong2*)gp         = make_ulonglong2(acc[i][0], acc[i][1]);
                *(ulonglong2*)(gp + 128) = make_ulonglong2(acc[i][2], acc[i][3]);
            }
            gridbar(phase);
        }

        // ---- phase2: out[s] = tanh(xproj + sum_p partial), 512 el per CTA
        if (tid < 128) {
            const size_t e4 = (size_t)bi * 128 + tid;   // float4 index in BH/4
            float4* o4 = (float4*)outs + (size_t)s * (BH / 4) + e4;
            float4 v = *o4;
            if (s > 0) {
                const float4* gp4 = (const float4*)g_partial + e4;
                float4 s0 = make_float4(0.f, 0.f, 0.f, 0.f);
                float4 s1 = make_float4(0.f, 0.f, 0.f, 0.f);
#pragma unroll
                for (int p = 0; p < KSLICES; p += 2) {
                    float4 q0 = __ldcg(gp4 + (size_t)p * (BH / 4));
                    float4 q1 = __ldcg(gp4 + (size_t)(p + 1) * (BH / 4));
                    s0.x += q0.x; s0.y += q0.y; s0.z += q0.z; s0.w += q0.w;
                    s1.x += q1.x; s1.y += q1.y; s1.z += q1.z; s1.w += q1.w;
                }
                v.x += s0.x + s1.x; v.y += s0.y + s1.y;
                v.z += s0.z + s1.z; v.w += s0.w + s1.w;
            }
            v.x = tanhf(v.x); v.y = tanhf(v.y);
            v.z = tanhf(v.z); v.w = tanhf(v.w);
            *o4 = v;
        }
        gridbar(phase);
    }

    // Final hidden = outputs[SEQ-1] appended after outputs region
    if (write_hidden) {
#pragma unroll
        for (int t = 0; t < 2; t++) {
            int idx = bi * 512 + t * 256 + tid;
            outs[(size_t)SBH + idx] = outs[(size_t)(SEQ - 1) * BH + idx];
        }
    }
}

// ---------------------------------------------------------------------------
// Launch. Inputs: X [B,S,E] f32, W_ax [H,E] f32, W_aa [H,H] f32, b_a [H] f32.
// Output: outputs [S,B,H] then hidden [B,H].
// ---------------------------------------------------------------------------
extern "C" void kernel_launch(void* const* d_in, const int* in_sizes, int n_in,
                              void* d_out, int out_size) {
    (void)in_sizes; (void)n_in;
    const float* X   = (const float*)d_in[0];
    const float* Wax = (const float*)d_in[1];
    const float* Waa = (const float*)d_in[2];
    const float* ba  = (const float*)d_in[3];
    float* out = (float*)d_out;

    void* cntp = nullptr;
    cudaGetSymbolAddress(&cntp, g_cnt);
    cudaMemsetAsync(cntp, 0, 256 * sizeof(unsigned), 0);

    dim3 g1((SEQ * BATCH) / 128, HID / 128);
    xproj_kernel<<<g1, 256>>>(X, Wax, ba, out);

    int write_hidden = (out_size >= (int)(SBH + BH)) ? 1 : 0;
    rnn_persistent<<<NBLOCKS, 256>>>(Waa, out, write_hidden);
}